// round 7
// baseline (speedup 1.0000x reference)
#include <cuda_runtime.h>
#include <cstddef>
#include <cstdint>

#define NN 50000
#define HD 64
#define EMAX 800000
#define FULLMASK 0xffffffffu

// ---- scratch (device globals) ----
__device__ __align__(256) float g_h[NN * HD];     // xp (layer input / output)
__device__ __align__(256) float g_hn[NN * HD];    // h = xp @ W
__device__ __align__(256) float g_proj[NN * HD];  // xp @ projW + projb
__device__ float g_asn[NN];
__device__ float g_adn[NN];
__device__ float g_pool[64 * 32];                 // padded: channel c at c*32
__device__ int   g_cnt[NN];
__device__ int   g_off[NN + 1];
__device__ int   g_cur[NN];
__device__ int2  g_sd[EMAX];                      // (src, dst) sorted by dst
__device__ int2  g_ew[EMAX];                      // (src, float_bits(w)) sorted by dst

__device__ __forceinline__ float lrelu(float x) { return x > 0.f ? x : 0.2f * x; }

__device__ __forceinline__ uint32_t f2tf32(float f) {
    uint32_t r;
    asm("cvt.rna.tf32.f32 %0, %1;" : "=r"(r) : "f"(f));
    return r;
}

__device__ __forceinline__ void mma_tf32(float c[4], uint32_t a0, uint32_t a1,
                                         uint32_t a2, uint32_t a3,
                                         uint32_t b0, uint32_t b1) {
    asm volatile(
        "mma.sync.aligned.m16n8k8.row.col.f32.tf32.tf32.f32 "
        "{%0,%1,%2,%3}, {%4,%5,%6,%7}, {%8,%9}, {%0,%1,%2,%3};"
        : "+f"(c[0]), "+f"(c[1]), "+f"(c[2]), "+f"(c[3])
        : "r"(a0), "r"(a1), "r"(a2), "r"(a3), "r"(b0), "r"(b1));
}

// ============================================================================
// CSR build (once per launch)
// ============================================================================
__global__ void zero_kernel() {
    int i = blockIdx.x * blockDim.x + threadIdx.x;
    if (i < NN) g_cnt[i] = 0;
    if (blockIdx.x == 0 && threadIdx.x < 64) g_pool[threadIdx.x * 32] = 0.f;
}

__global__ void hist_kernel(const int* __restrict__ ei, int E) {
    int j = blockIdx.x * blockDim.x + threadIdx.x;
    if (j >= E) return;
    atomicAdd(&g_cnt[ei[E + j]], 1);
}

__global__ void scan_kernel() {   // single block, 1024 threads
    __shared__ int wsum[32];
    __shared__ int sbase;
    int tid = threadIdx.x, lane = tid & 31, warp = tid >> 5;
    if (tid == 0) sbase = 0;
    __syncthreads();
    for (int base = 0; base < NN; base += 1024) {
        int i = base + tid;
        int c = (i < NN) ? g_cnt[i] : 0;
        int v = c;
        #pragma unroll
        for (int o = 1; o < 32; o <<= 1) {
            int t = __shfl_up_sync(FULLMASK, v, o);
            if (lane >= o) v += t;
        }
        if (lane == 31) wsum[warp] = v;
        __syncthreads();
        if (warp == 0) {
            int w = wsum[lane];
            #pragma unroll
            for (int o = 1; o < 32; o <<= 1) {
                int t = __shfl_up_sync(FULLMASK, w, o);
                if (lane >= o) w += t;
            }
            wsum[lane] = w;
        }
        __syncthreads();
        int warpoff = warp ? wsum[warp - 1] : 0;
        int total = wsum[31];
        int excl = sbase + warpoff + v - c;
        if (i < NN) { g_off[i] = excl; g_cur[i] = excl; }
        __syncthreads();
        if (tid == 0) sbase += total;
        __syncthreads();
    }
    if (threadIdx.x == 0) g_off[NN] = sbase;
}

__global__ void sortedge_kernel(const int* __restrict__ ei, int E) {
    int j = blockIdx.x * blockDim.x + threadIdx.x;
    if (j >= E) return;
    int src = ei[j];
    int dst = ei[E + j];
    int pos = atomicAdd(&g_cur[dst], 1);
    if (pos < EMAX) g_sd[pos] = make_int2(src, dst);
}

// ============================================================================
// K1: tensor-core GEMM, 3xTF32 split precision (error ~2^-22 ~ fp32):
//   h = xp @ W [+ proj = xp @ projW] + attention scalars.
// Block = 128 nodes x 64 cols; warp = 16 rows. xs stride K+4, Ws stride 72.
// ============================================================================
template <int KDIM, bool HAS_PROJ>
__global__ void __launch_bounds__(256)
gemm_mma_kernel(const float* __restrict__ xp,
                const float* __restrict__ W,
                const float* __restrict__ a_s,
                const float* __restrict__ a_d,
                const float* __restrict__ projW,
                const float* __restrict__ projb) {
    constexpr int ST = KDIM + 4;
    extern __shared__ uint32_t dsm[];
    uint32_t* xsh = dsm;                        // [128][ST] hi
    uint32_t* xsl = xsh + 128 * ST;             // [128][ST] lo
    uint32_t* Wsh = xsl + 128 * ST;             // [KDIM][72] hi
    uint32_t* Wsl = Wsh + KDIM * 72;            // [KDIM][72] lo
    uint32_t* Psh = Wsl + KDIM * 72;            // proj hi (HAS_PROJ)
    uint32_t* Psl = Psh + (HAS_PROJ ? KDIM * 72 : 0);

    int tid = threadIdx.x;
    int nbase = blockIdx.x * 128;
    const float* src = xp ? xp : g_h;

    // stage X -> split tf32 smem
    for (int i = tid; i < 128 * KDIM; i += 256) {
        int r = i / KDIM, cc = i % KDIM;
        int n = nbase + r;
        float v = (n < NN) ? src[(size_t)n * KDIM + cc] : 0.f;
        uint32_t hi = f2tf32(v);
        xsh[r * ST + cc] = hi;
        xsl[r * ST + cc] = f2tf32(v - __uint_as_float(hi));
    }
    // stage W (and P) -> split tf32 smem
    for (int i = tid; i < KDIM * 64; i += 256) {
        int k = i >> 6, n = i & 63;
        float wv = W[i];
        uint32_t hi = f2tf32(wv);
        Wsh[k * 72 + n] = hi;
        Wsl[k * 72 + n] = f2tf32(wv - __uint_as_float(hi));
        if (HAS_PROJ) {
            float pv = projW[i];
            uint32_t ph = f2tf32(pv);
            Psh[k * 72 + n] = ph;
            Psl[k * 72 + n] = f2tf32(pv - __uint_as_float(ph));
        }
    }
    __syncthreads();

    int warp = tid >> 5, lane = tid & 31;
    int r = lane >> 2, c = lane & 3;
    int rbase = warp * 16;

    float cw[8][4];
    float cp[8][4];
    #pragma unroll
    for (int t = 0; t < 8; t++) {
        #pragma unroll
        for (int q = 0; q < 4; q++) { cw[t][q] = 0.f; cp[t][q] = 0.f; }
    }

    #pragma unroll 1
    for (int kb = 0; kb < KDIM; kb += 8) {
        uint32_t ah0 = xsh[(rbase + r) * ST + kb + c];
        uint32_t ah1 = xsh[(rbase + r + 8) * ST + kb + c];
        uint32_t ah2 = xsh[(rbase + r) * ST + kb + 4 + c];
        uint32_t ah3 = xsh[(rbase + r + 8) * ST + kb + 4 + c];
        uint32_t al0 = xsl[(rbase + r) * ST + kb + c];
        uint32_t al1 = xsl[(rbase + r + 8) * ST + kb + c];
        uint32_t al2 = xsl[(rbase + r) * ST + kb + 4 + c];
        uint32_t al3 = xsl[(rbase + r + 8) * ST + kb + 4 + c];
        #pragma unroll
        for (int t = 0; t < 8; t++) {
            uint32_t bh0 = Wsh[(kb + c) * 72 + t * 8 + r];
            uint32_t bh1 = Wsh[(kb + 4 + c) * 72 + t * 8 + r];
            uint32_t bl0 = Wsl[(kb + c) * 72 + t * 8 + r];
            uint32_t bl1 = Wsl[(kb + 4 + c) * 72 + t * 8 + r];
            mma_tf32(cw[t], ah0, ah1, ah2, ah3, bl0, bl1);
            mma_tf32(cw[t], al0, al1, al2, al3, bh0, bh1);
            mma_tf32(cw[t], ah0, ah1, ah2, ah3, bh0, bh1);
            if (HAS_PROJ) {
                uint32_t qh0 = Psh[(kb + c) * 72 + t * 8 + r];
                uint32_t qh1 = Psh[(kb + 4 + c) * 72 + t * 8 + r];
                uint32_t ql0 = Psl[(kb + c) * 72 + t * 8 + r];
                uint32_t ql1 = Psl[(kb + 4 + c) * 72 + t * 8 + r];
                mma_tf32(cp[t], ah0, ah1, ah2, ah3, ql0, ql1);
                mma_tf32(cp[t], al0, al1, al2, al3, qh0, qh1);
                mma_tf32(cp[t], ah0, ah1, ah2, ah3, qh0, qh1);
            }
        }
    }

    int n0 = nbase + rbase + r;
    int n1 = n0 + 8;
    float s0 = 0.f, s8 = 0.f, d0 = 0.f, d8 = 0.f;
    #pragma unroll
    for (int t = 0; t < 8; t++) {
        int col = t * 8 + 2 * c;
        float A0 = __ldg(&a_s[col]), A1 = __ldg(&a_s[col + 1]);
        float D0 = __ldg(&a_d[col]), D1 = __ldg(&a_d[col + 1]);
        s0 += cw[t][0] * A0 + cw[t][1] * A1;
        s8 += cw[t][2] * A0 + cw[t][3] * A1;
        d0 += cw[t][0] * D0 + cw[t][1] * D1;
        d8 += cw[t][2] * D0 + cw[t][3] * D1;
        if (n0 < NN) *(float2*)(g_hn + (size_t)n0 * 64 + col) = make_float2(cw[t][0], cw[t][1]);
        if (n1 < NN) *(float2*)(g_hn + (size_t)n1 * 64 + col) = make_float2(cw[t][2], cw[t][3]);
        if (HAS_PROJ) {
            float pb0 = __ldg(&projb[col]), pb1 = __ldg(&projb[col + 1]);
            if (n0 < NN) *(float2*)(g_proj + (size_t)n0 * 64 + col) = make_float2(cp[t][0] + pb0, cp[t][1] + pb1);
            if (n1 < NN) *(float2*)(g_proj + (size_t)n1 * 64 + col) = make_float2(cp[t][2] + pb0, cp[t][3] + pb1);
        }
    }
    // reduce across the 4 lanes that share row r
    s0 += __shfl_xor_sync(FULLMASK, s0, 1); s0 += __shfl_xor_sync(FULLMASK, s0, 2);
    s8 += __shfl_xor_sync(FULLMASK, s8, 1); s8 += __shfl_xor_sync(FULLMASK, s8, 2);
    d0 += __shfl_xor_sync(FULLMASK, d0, 1); d0 += __shfl_xor_sync(FULLMASK, d0, 2);
    d8 += __shfl_xor_sync(FULLMASK, d8, 1); d8 += __shfl_xor_sync(FULLMASK, d8, 2);
    if (c == 0) {
        if (n0 < NN) { g_asn[n0] = s0; g_adn[n0] = d0; }
        if (n1 < NN) { g_asn[n1] = s8; g_adn[n1] = d8; }
    }
}

// ============================================================================
// K2: flat per-edge weight precompute; packs (src, w) for the gather.
// ============================================================================
__global__ void edgew_kernel(int E) {
    int p = blockIdx.x * blockDim.x + threadIdx.x;
    if (p >= E) return;
    int2 sd = g_sd[p];
    float w = __expf(lrelu(g_asn[sd.x] + g_adn[sd.y]));
    g_ew[p] = make_int2(sd.x, __float_as_int(w));
}

// ============================================================================
// K3: aggregate — ONE node per warp. Coalesced (src,w) via one LDG.64/lane,
// distributed by shuffles; per-edge work = one float2 gather + 2 FMA.
// ============================================================================
template <bool HAS_PROJ, bool DO_POOL>
__global__ void aggregate_kernel(const float* __restrict__ bias,
                                 const float* __restrict__ bng, const float* __restrict__ bnb,
                                 const float* __restrict__ bnm, const float* __restrict__ bnv) {
    __shared__ float bsum[64];
    int tid = threadIdx.x;
    if (DO_POOL) {
        if (tid < 64) bsum[tid] = 0.f;
        __syncthreads();
    }

    int warp = tid >> 5, lane = tid & 31;
    int n = blockIdx.x * 8 + warp;
    if (n < NN) {
        int c0 = lane * 2, c1 = c0 + 1;
        int start = g_off[n], end = g_off[n + 1];
        float adn_n = g_adn[n];
        float wself = __expf(lrelu(g_asn[n] + adn_n));
        float2 hvs = *(const float2*)(g_hn + (size_t)n * 64 + c0);
        float accx = wself * hvs.x;
        float accy = wself * hvs.y;
        float denom = wself;

        for (int base = start; base < end; base += 32) {
            int m = end - base;
            int cnt = m < 32 ? m : 32;
            int2 ew = (lane < m) ? __ldg(&g_ew[base + lane]) : make_int2(0, 0);
            int idx = ew.x;
            float wv = __int_as_float(ew.y);

            float ws = wv;
            #pragma unroll
            for (int o = 16; o > 0; o >>= 1)
                ws += __shfl_xor_sync(FULLMASK, ws, o);
            denom += ws;

            int e = 0;
            for (; e + 8 <= cnt; e += 8) {
                #pragma unroll
                for (int u = 0; u < 8; u++) {
                    int s  = __shfl_sync(FULLMASK, idx, e + u);
                    float w = __shfl_sync(FULLMASK, wv, e + u);
                    float2 hv = *(const float2*)(g_hn + (size_t)s * 64 + c0);
                    accx = fmaf(w, hv.x, accx);
                    accy = fmaf(w, hv.y, accy);
                }
            }
            for (; e < cnt; e++) {
                int s  = __shfl_sync(FULLMASK, idx, e);
                float w = __shfl_sync(FULLMASK, wv, e);
                float2 hv = *(const float2*)(g_hn + (size_t)s * 64 + c0);
                accx = fmaf(w, hv.x, accx);
                accy = fmaf(w, hv.y, accy);
            }
        }

        float sc0 = bng[c0] * rsqrtf(bnv[c0] + 1e-5f);
        float sc1 = bng[c1] * rsqrtf(bnv[c1] + 1e-5f);
        float sh0 = bnb[c0] - bnm[c0] * sc0;
        float sh1 = bnb[c1] - bnm[c1] * sc1;

        float inv = 1.f / (denom + 1e-16f);
        float o0 = accx * inv + bias[c0];
        float o1 = accy * inv + bias[c1];
        o0 = o0 > 0.f ? o0 : 0.f;
        o1 = o1 > 0.f ? o1 : 0.f;
        float y0 = o0 * sc0 + sh0;
        float y1 = o1 * sc1 + sh1;

        if (HAS_PROJ) {
            float2 pv = *(const float2*)(g_proj + (size_t)n * 64 + c0);
            y0 += pv.x; y1 += pv.y;
        }

        *(float2*)(g_h + (size_t)n * 64 + c0) = make_float2(y0, y1);
        if (DO_POOL) {
            atomicAdd(&bsum[c0], y0);
            atomicAdd(&bsum[c1], y1);
        }
    }
    if (DO_POOL) {
        __syncthreads();
        if (tid < 64) atomicAdd(&g_pool[tid * 32], bsum[tid]);
    }
}

// ============================================================================
// Head
// ============================================================================
__global__ void head_kernel(const float* __restrict__ hW1, const float* __restrict__ hb1,
                            const float* __restrict__ hg, const float* __restrict__ hbb,
                            const float* __restrict__ hm, const float* __restrict__ hv,
                            const float* __restrict__ hW2, const float* __restrict__ hb2,
                            float* __restrict__ out) {
    __shared__ float gsh[64];
    __shared__ float h1[32];
    int t = threadIdx.x;
    if (t < 64) gsh[t] = g_pool[t * 32] * (1.f / (float)NN);
    __syncthreads();
    if (t < 32) {
        float acc = hb1[t];
        #pragma unroll 8
        for (int k = 0; k < 64; k++) acc = fmaf(gsh[k], hW1[k * 32 + t], acc);
        acc = acc > 0.f ? acc : 0.f;
        float sc = hg[t] * rsqrtf(hv[t] + 1e-5f);
        h1[t] = (acc - hm[t]) * sc + hbb[t];
    }
    __syncthreads();
    if (t == 0) {
        float acc = hb2[0];
        #pragma unroll
        for (int j = 0; j < 32; j++) acc = fmaf(h1[j], hW2[j], acc);
        out[0] = acc;
    }
}

// ============================================================================
extern "C" void kernel_launch(void* const* d_in, const int* in_sizes, int n_in,
                              void* d_out, int out_size) {
    const float* x        = (const float*)d_in[0];
    const int*   ei       = (const int*)d_in[1];
    const float* conv1_W  = (const float*)d_in[2];
    const float* conv1_as = (const float*)d_in[3];
    const float* conv1_ad = (const float*)d_in[4];
    const float* conv1_b  = (const float*)d_in[5];
    const float* convW    = (const float*)d_in[6];
    const float* conv_as  = (const float*)d_in[7];
    const float* conv_ad  = (const float*)d_in[8];
    const float* conv_b   = (const float*)d_in[9];
    const float* bn_g     = (const float*)d_in[10];
    const float* bn_b     = (const float*)d_in[11];
    const float* bn_m     = (const float*)d_in[12];
    const float* bn_v     = (const float*)d_in[13];
    const float* projW    = (const float*)d_in[14];
    const float* projb    = (const float*)d_in[15];
    const float* hW1      = (const float*)d_in[16];
    const float* hb1      = (const float*)d_in[17];
    const float* hbn_g    = (const float*)d_in[18];
    const float* hbn_b    = (const float*)d_in[19];
    const float* hbn_m    = (const float*)d_in[20];
    const float* hbn_v    = (const float*)d_in[21];
    const float* hW2      = (const float*)d_in[22];
    const float* hb2      = (const float*)d_in[23];

    int E = in_sizes[1] / 2;

    const int edge_blocks = (E + 255) / 256;
    const int agg_blocks  = (NN + 7) / 8;      // ONE node per warp
    const int gemm_blocks = (NN + 127) / 128;  // 128 nodes per block

    const int smem1 = (2 * 128 * (128 + 4) + 2 * 128 * 72) * 4;   // 208896 B
    const int smem2 = (2 * 128 * (64 + 4) + 4 * 64 * 72) * 4;     // 143360 B
    cudaFuncSetAttribute((const void*)gemm_mma_kernel<128, false>,
                         cudaFuncAttributeMaxDynamicSharedMemorySize, smem1);
    cudaFuncSetAttribute((const void*)gemm_mma_kernel<64, true>,
                         cudaFuncAttributeMaxDynamicSharedMemorySize, smem2);

    // ---- CSR build; layer-1 GEMM placed 4th (no CSR dependency) ----
    zero_kernel<<<(NN + 255) / 256, 256>>>();
    hist_kernel<<<edge_blocks, 256>>>(ei, E);
    scan_kernel<<<1, 1024>>>();
    gemm_mma_kernel<128, false><<<gemm_blocks, 256, smem1>>>(x, conv1_W, conv1_as, conv1_ad,
                                                             nullptr, nullptr);
    sortedge_kernel<<<edge_blocks, 256>>>(ei, E);
    edgew_kernel<<<edge_blocks, 256>>>(E);
    aggregate_kernel<false, false><<<agg_blocks, 256>>>(conv1_b, bn_g, bn_b, bn_m, bn_v);

    // ---- layers 2..5 (fused proj GEMM) ----
    for (int l = 0; l < 4; l++) {
        gemm_mma_kernel<64, true><<<gemm_blocks, 256, smem2>>>(nullptr, convW + l * 4096,
                                                               conv_as + l * 64, conv_ad + l * 64,
                                                               projW + l * 4096, projb + l * 64);
        edgew_kernel<<<edge_blocks, 256>>>(E);
        if (l == 3)
            aggregate_kernel<true, true><<<agg_blocks, 256>>>(conv_b + l * 64,
                bn_g + (l + 1) * 64, bn_b + (l + 1) * 64, bn_m + (l + 1) * 64, bn_v + (l + 1) * 64);
        else
            aggregate_kernel<true, false><<<agg_blocks, 256>>>(conv_b + l * 64,
                bn_g + (l + 1) * 64, bn_b + (l + 1) * 64, bn_m + (l + 1) * 64, bn_v + (l + 1) * 64);
    }

    // ---- head ----
    head_kernel<<<1, 64>>>(hW1, hb1, hbn_g, hbn_b, hbn_m, hbn_v, hW2, hb2, (float*)d_out);
}

// round 10
// speedup vs baseline: 1.1273x; 1.1273x over previous
#include <cuda_runtime.h>
#include <cstddef>
#include <cstdint>

#define NN 50000
#define HD 64
#define EMAX 800000
#define FULLMASK 0xffffffffu

// ---- scratch (device globals) ----
__device__ __align__(256) float g_h[NN * HD];     // xp (layer input / output)
__device__ __align__(256) float g_hn[NN * HD];    // h = xp @ W
__device__ __align__(256) float g_proj[NN * HD];  // xp @ projW + projb
__device__ float g_asn[NN];
__device__ float g_adn[NN];
__device__ float g_pool[64 * 32];                 // padded: channel c at c*32
__device__ int   g_cnt[NN];
__device__ int   g_off[NN + 1];
__device__ int   g_cur[NN];
__device__ int2  g_sd[EMAX];                      // (src, dst) sorted by dst
__device__ int2  g_ew[EMAX];                      // (src, float_bits(w)) sorted by dst

__device__ __forceinline__ float lrelu(float x) { return x > 0.f ? x : 0.2f * x; }

__device__ __forceinline__ uint32_t f2tf32(float f) {
    uint32_t r;
    asm("cvt.rna.tf32.f32 %0, %1;" : "=r"(r) : "f"(f));
    return r;
}

__device__ __forceinline__ void splitf(float v, uint32_t& hi, uint32_t& lo) {
    hi = f2tf32(v);
    lo = f2tf32(v - __uint_as_float(hi));
}

__device__ __forceinline__ void mma_tf32(float c[4], uint32_t a0, uint32_t a1,
                                         uint32_t a2, uint32_t a3,
                                         uint32_t b0, uint32_t b1) {
    asm volatile(
        "mma.sync.aligned.m16n8k8.row.col.f32.tf32.tf32.f32 "
        "{%0,%1,%2,%3}, {%4,%5,%6,%7}, {%8,%9}, {%0,%1,%2,%3};"
        : "+f"(c[0]), "+f"(c[1]), "+f"(c[2]), "+f"(c[3])
        : "r"(a0), "r"(a1), "r"(a2), "r"(a3), "r"(b0), "r"(b1));
}

// ============================================================================
// CSR build (once per launch)
// ============================================================================
__global__ void zero_kernel() {
    int i = blockIdx.x * blockDim.x + threadIdx.x;
    if (i < NN) g_cnt[i] = 0;
    if (blockIdx.x == 0 && threadIdx.x < 64) g_pool[threadIdx.x * 32] = 0.f;
}

__global__ void hist_kernel(const int* __restrict__ ei, int E) {
    int j = blockIdx.x * blockDim.x + threadIdx.x;
    if (j >= E) return;
    atomicAdd(&g_cnt[ei[E + j]], 1);
}

__global__ void scan_kernel() {   // single block, 1024 threads
    __shared__ int wsum[32];
    __shared__ int sbase;
    int tid = threadIdx.x, lane = tid & 31, warp = tid >> 5;
    if (tid == 0) sbase = 0;
    __syncthreads();
    for (int base = 0; base < NN; base += 1024) {
        int i = base + tid;
        int c = (i < NN) ? g_cnt[i] : 0;
        int v = c;
        #pragma unroll
        for (int o = 1; o < 32; o <<= 1) {
            int t = __shfl_up_sync(FULLMASK, v, o);
            if (lane >= o) v += t;
        }
        if (lane == 31) wsum[warp] = v;
        __syncthreads();
        if (warp == 0) {
            int w = wsum[lane];
            #pragma unroll
            for (int o = 1; o < 32; o <<= 1) {
                int t = __shfl_up_sync(FULLMASK, w, o);
                if (lane >= o) w += t;
            }
            wsum[lane] = w;
        }
        __syncthreads();
        int warpoff = warp ? wsum[warp - 1] : 0;
        int total = wsum[31];
        int excl = sbase + warpoff + v - c;
        if (i < NN) { g_off[i] = excl; g_cur[i] = excl; }
        __syncthreads();
        if (tid == 0) sbase += total;
        __syncthreads();
    }
    if (threadIdx.x == 0) g_off[NN] = sbase;
}

__global__ void sortedge_kernel(const int* __restrict__ ei, int E) {
    int j = blockIdx.x * blockDim.x + threadIdx.x;
    if (j >= E) return;
    int src = ei[j];
    int dst = ei[E + j];
    int pos = atomicAdd(&g_cur[dst], 1);
    if (pos < EMAX) g_sd[pos] = make_int2(src, dst);
}

// ============================================================================
// K1: tensor-core GEMM, 3xTF32 split precision (~fp32 accuracy).
// x kept fp32 in smem (split on the fly); W/proj pre-split hi/lo in smem.
// COLSPLIT (layer 1, ROWS=64): warps tile rows x col-halves; attention sums
// combined via smem. Else (ROWS=128): warp owns 16 rows x all 64 cols.
// smem ~108KB -> 2 blocks/SM.
// ============================================================================
template <int KDIM, int ROWS, bool COLSPLIT, bool HAS_PROJ>
__global__ void __launch_bounds__(256)
gemm_mma_kernel(const float* __restrict__ xp,
                const float* __restrict__ W,
                const float* __restrict__ a_s,
                const float* __restrict__ a_d,
                const float* __restrict__ projW,
                const float* __restrict__ projb) {
    constexpr int ST = KDIM + 4;
    constexpr int NT = COLSPLIT ? 4 : 8;     // 8-col tiles per warp
    extern __shared__ float dsm[];
    float* xs = dsm;                                   // [ROWS][ST] fp32
    uint32_t* Wsh = (uint32_t*)(xs + ROWS * ST);       // [KDIM][72]
    uint32_t* Wsl = Wsh + KDIM * 72;
    uint32_t* Psh = Wsl + KDIM * 72;
    uint32_t* Psl = Psh + (HAS_PROJ ? KDIM * 72 : 0);
    float* sred = (float*)(Psl + (HAS_PROJ ? KDIM * 72 : 0));  // [2][64][2]

    int tid = threadIdx.x;
    int nbase = blockIdx.x * ROWS;
    const float* src = xp ? xp : g_h;

    for (int i = tid; i < ROWS * KDIM; i += 256) {
        int r = i / KDIM, cc = i % KDIM;
        int n = nbase + r;
        xs[r * ST + cc] = (n < NN) ? src[(size_t)n * KDIM + cc] : 0.f;
    }
    for (int i = tid; i < KDIM * 64; i += 256) {
        int k = i >> 6, n = i & 63;
        uint32_t hi, lo;
        splitf(W[i], hi, lo);
        Wsh[k * 72 + n] = hi;
        Wsl[k * 72 + n] = lo;
        if (HAS_PROJ) {
            splitf(projW[i], hi, lo);
            Psh[k * 72 + n] = hi;
            Psl[k * 72 + n] = lo;
        }
    }
    __syncthreads();

    int warp = tid >> 5, lane = tid & 31;
    int r = lane >> 2, c = lane & 3;
    int rowg = COLSPLIT ? (warp & 3) * 16 : warp * 16;
    int colg = COLSPLIT ? (warp >> 2) * 32 : 0;

    float cw[NT][4], cp[NT][4];
    #pragma unroll
    for (int t = 0; t < NT; t++) {
        #pragma unroll
        for (int q = 0; q < 4; q++) { cw[t][q] = 0.f; cp[t][q] = 0.f; }
    }

    #pragma unroll 1
    for (int kb = 0; kb < KDIM; kb += 8) {
        uint32_t ah0, al0, ah1, al1, ah2, al2, ah3, al3;
        splitf(xs[(rowg + r) * ST + kb + c], ah0, al0);
        splitf(xs[(rowg + r + 8) * ST + kb + c], ah1, al1);
        splitf(xs[(rowg + r) * ST + kb + 4 + c], ah2, al2);
        splitf(xs[(rowg + r + 8) * ST + kb + 4 + c], ah3, al3);
        #pragma unroll
        for (int t = 0; t < NT; t++) {
            int cb = colg + t * 8 + r;
            uint32_t bh0 = Wsh[(kb + c) * 72 + cb];
            uint32_t bh1 = Wsh[(kb + 4 + c) * 72 + cb];
            uint32_t bl0 = Wsl[(kb + c) * 72 + cb];
            uint32_t bl1 = Wsl[(kb + 4 + c) * 72 + cb];
            mma_tf32(cw[t], ah0, ah1, ah2, ah3, bl0, bl1);
            mma_tf32(cw[t], al0, al1, al2, al3, bh0, bh1);
            mma_tf32(cw[t], ah0, ah1, ah2, ah3, bh0, bh1);
            if (HAS_PROJ) {
                uint32_t qh0 = Psh[(kb + c) * 72 + cb];
                uint32_t qh1 = Psh[(kb + 4 + c) * 72 + cb];
                uint32_t ql0 = Psl[(kb + c) * 72 + cb];
                uint32_t ql1 = Psl[(kb + 4 + c) * 72 + cb];
                mma_tf32(cp[t], ah0, ah1, ah2, ah3, ql0, ql1);
                mma_tf32(cp[t], al0, al1, al2, al3, qh0, qh1);
                mma_tf32(cp[t], ah0, ah1, ah2, ah3, qh0, qh1);
            }
        }
    }

    int n0 = nbase + rowg + r;
    int n1 = n0 + 8;
    float s0 = 0.f, s8 = 0.f, d0 = 0.f, d8 = 0.f;
    #pragma unroll
    for (int t = 0; t < NT; t++) {
        int col = colg + t * 8 + 2 * c;
        float A0 = __ldg(&a_s[col]), A1 = __ldg(&a_s[col + 1]);
        float D0 = __ldg(&a_d[col]), D1 = __ldg(&a_d[col + 1]);
        s0 += cw[t][0] * A0 + cw[t][1] * A1;
        s8 += cw[t][2] * A0 + cw[t][3] * A1;
        d0 += cw[t][0] * D0 + cw[t][1] * D1;
        d8 += cw[t][2] * D0 + cw[t][3] * D1;
        if (n0 < NN) *(float2*)(g_hn + (size_t)n0 * 64 + col) = make_float2(cw[t][0], cw[t][1]);
        if (n1 < NN) *(float2*)(g_hn + (size_t)n1 * 64 + col) = make_float2(cw[t][2], cw[t][3]);
        if (HAS_PROJ) {
            float pb0 = __ldg(&projb[col]), pb1 = __ldg(&projb[col + 1]);
            if (n0 < NN) *(float2*)(g_proj + (size_t)n0 * 64 + col) = make_float2(cp[t][0] + pb0, cp[t][1] + pb1);
            if (n1 < NN) *(float2*)(g_proj + (size_t)n1 * 64 + col) = make_float2(cp[t][2] + pb0, cp[t][3] + pb1);
        }
    }
    // reduce across the 4 lanes sharing a row
    s0 += __shfl_xor_sync(FULLMASK, s0, 1); s0 += __shfl_xor_sync(FULLMASK, s0, 2);
    s8 += __shfl_xor_sync(FULLMASK, s8, 1); s8 += __shfl_xor_sync(FULLMASK, s8, 2);
    d0 += __shfl_xor_sync(FULLMASK, d0, 1); d0 += __shfl_xor_sync(FULLMASK, d0, 2);
    d8 += __shfl_xor_sync(FULLMASK, d8, 1); d8 += __shfl_xor_sync(FULLMASK, d8, 2);

    if (COLSPLIT) {
        int cg = warp >> 2;
        if (c == 0) {
            int row0 = rowg + r, row1 = rowg + r + 8;
            sred[cg * 128 + row0 * 2]     = s0;
            sred[cg * 128 + row0 * 2 + 1] = d0;
            sred[cg * 128 + row1 * 2]     = s8;
            sred[cg * 128 + row1 * 2 + 1] = d8;
        }
        __syncthreads();
        if (tid < ROWS) {
            int n = nbase + tid;
            if (n < NN) {
                g_asn[n] = sred[tid * 2] + sred[128 + tid * 2];
                g_adn[n] = sred[tid * 2 + 1] + sred[128 + tid * 2 + 1];
            }
        }
    } else {
        if (c == 0) {
            if (n0 < NN) { g_asn[n0] = s0; g_adn[n0] = d0; }
            if (n1 < NN) { g_asn[n1] = s8; g_adn[n1] = d8; }
        }
    }
}

// ============================================================================
// K2: flat per-edge weight precompute; packs (src, w) for the gather.
// ============================================================================
__global__ void edgew_kernel(int E) {
    int p = blockIdx.x * blockDim.x + threadIdx.x;
    if (p >= E) return;
    int2 sd = g_sd[p];
    float w = __expf(lrelu(g_asn[sd.x] + g_adn[sd.y]));
    g_ew[p] = make_int2(sd.x, __float_as_int(w));
}

// ============================================================================
// K3: aggregate — ONE node per warp. Coalesced (src,w) via one LDG.64/lane,
// distributed by shuffles; per-edge work = one float2 gather + 2 FMA.
// ============================================================================
template <bool HAS_PROJ, bool DO_POOL>
__global__ void aggregate_kernel(const float* __restrict__ bias,
                                 const float* __restrict__ bng, const float* __restrict__ bnb,
                                 const float* __restrict__ bnm, const float* __restrict__ bnv) {
    __shared__ float bsum[64];
    int tid = threadIdx.x;
    if (DO_POOL) {
        if (tid < 64) bsum[tid] = 0.f;
        __syncthreads();
    }

    int warp = tid >> 5, lane = tid & 31;
    int n = blockIdx.x * 8 + warp;
    if (n < NN) {
        int c0 = lane * 2, c1 = c0 + 1;
        int start = g_off[n], end = g_off[n + 1];
        float adn_n = g_adn[n];
        float wself = __expf(lrelu(g_asn[n] + adn_n));
        float2 hvs = *(const float2*)(g_hn + (size_t)n * 64 + c0);
        float accx = wself * hvs.x;
        float accy = wself * hvs.y;
        float denom = wself;

        for (int base = start; base < end; base += 32) {
            int m = end - base;
            int cnt = m < 32 ? m : 32;
            int2 ew = (lane < m) ? __ldg(&g_ew[base + lane]) : make_int2(0, 0);
            int idx = ew.x;
            float wv = __int_as_float(ew.y);

            float ws = wv;
            #pragma unroll
            for (int o = 16; o > 0; o >>= 1)
                ws += __shfl_xor_sync(FULLMASK, ws, o);
            denom += ws;

            int e = 0;
            for (; e + 8 <= cnt; e += 8) {
                #pragma unroll
                for (int u = 0; u < 8; u++) {
                    int s  = __shfl_sync(FULLMASK, idx, e + u);
                    float w = __shfl_sync(FULLMASK, wv, e + u);
                    float2 hv = *(const float2*)(g_hn + (size_t)s * 64 + c0);
                    accx = fmaf(w, hv.x, accx);
                    accy = fmaf(w, hv.y, accy);
                }
            }
            for (; e < cnt; e++) {
                int s  = __shfl_sync(FULLMASK, idx, e);
                float w = __shfl_sync(FULLMASK, wv, e);
                float2 hv = *(const float2*)(g_hn + (size_t)s * 64 + c0);
                accx = fmaf(w, hv.x, accx);
                accy = fmaf(w, hv.y, accy);
            }
        }

        float sc0 = bng[c0] * rsqrtf(bnv[c0] + 1e-5f);
        float sc1 = bng[c1] * rsqrtf(bnv[c1] + 1e-5f);
        float sh0 = bnb[c0] - bnm[c0] * sc0;
        float sh1 = bnb[c1] - bnm[c1] * sc1;

        float inv = 1.f / (denom + 1e-16f);
        float o0 = accx * inv + bias[c0];
        float o1 = accy * inv + bias[c1];
        o0 = o0 > 0.f ? o0 : 0.f;
        o1 = o1 > 0.f ? o1 : 0.f;
        float y0 = o0 * sc0 + sh0;
        float y1 = o1 * sc1 + sh1;

        if (HAS_PROJ) {
            float2 pv = *(const float2*)(g_proj + (size_t)n * 64 + c0);
            y0 += pv.x; y1 += pv.y;
        }

        *(float2*)(g_h + (size_t)n * 64 + c0) = make_float2(y0, y1);
        if (DO_POOL) {
            atomicAdd(&bsum[c0], y0);
            atomicAdd(&bsum[c1], y1);
        }
    }
    if (DO_POOL) {
        __syncthreads();
        if (tid < 64) atomicAdd(&g_pool[tid * 32], bsum[tid]);
    }
}

// ============================================================================
// Head
// ============================================================================
__global__ void head_kernel(const float* __restrict__ hW1, const float* __restrict__ hb1,
                            const float* __restrict__ hg, const float* __restrict__ hbb,
                            const float* __restrict__ hm, const float* __restrict__ hv,
                            const float* __restrict__ hW2, const float* __restrict__ hb2,
                            float* __restrict__ out) {
    __shared__ float gsh[64];
    __shared__ float h1[32];
    int t = threadIdx.x;
    if (t < 64) gsh[t] = g_pool[t * 32] * (1.f / (float)NN);
    __syncthreads();
    if (t < 32) {
        float acc = hb1[t];
        #pragma unroll 8
        for (int k = 0; k < 64; k++) acc = fmaf(gsh[k], hW1[k * 32 + t], acc);
        acc = acc > 0.f ? acc : 0.f;
        float sc = hg[t] * rsqrtf(hv[t] + 1e-5f);
        h1[t] = (acc - hm[t]) * sc + hbb[t];
    }
    __syncthreads();
    if (t == 0) {
        float acc = hb2[0];
        #pragma unroll
        for (int j = 0; j < 32; j++) acc = fmaf(h1[j], hW2[j], acc);
        out[0] = acc;
    }
}

// ============================================================================
extern "C" void kernel_launch(void* const* d_in, const int* in_sizes, int n_in,
                              void* d_out, int out_size) {
    const float* x        = (const float*)d_in[0];
    const int*   ei       = (const int*)d_in[1];
    const float* conv1_W  = (const float*)d_in[2];
    const float* conv1_as = (const float*)d_in[3];
    const float* conv1_ad = (const float*)d_in[4];
    const float* conv1_b  = (const float*)d_in[5];
    const float* convW    = (const float*)d_in[6];
    const float* conv_as  = (const float*)d_in[7];
    const float* conv_ad  = (const float*)d_in[8];
    const float* conv_b   = (const float*)d_in[9];
    const float* bn_g     = (const float*)d_in[10];
    const float* bn_b     = (const float*)d_in[11];
    const float* bn_m     = (const float*)d_in[12];
    const float* bn_v     = (const float*)d_in[13];
    const float* projW    = (const float*)d_in[14];
    const float* projb    = (const float*)d_in[15];
    const float* hW1      = (const float*)d_in[16];
    const float* hb1      = (const float*)d_in[17];
    const float* hbn_g    = (const float*)d_in[18];
    const float* hbn_b    = (const float*)d_in[19];
    const float* hbn_m    = (const float*)d_in[20];
    const float* hbn_v    = (const float*)d_in[21];
    const float* hW2      = (const float*)d_in[22];
    const float* hb2      = (const float*)d_in[23];

    int E = in_sizes[1] / 2;

    const int edge_blocks = (E + 255) / 256;
    const int agg_blocks  = (NN + 7) / 8;       // ONE node per warp
    const int g1_blocks   = (NN + 63) / 64;     // layer 1: 64 rows/block
    const int g2_blocks   = (NN + 127) / 128;   // layers 2-5: 128 rows/block

    // smem: layer1 = 64*132*4 + 2*128*72*4 + 1024 = 108544
    //       layers2-5 = 128*68*4 + 4*64*72*4 + 1024 = 109568  (both -> 2 blocks/SM)
    const int smem1 = (64 * 132 + 2 * 128 * 72 + 256) * 4;
    const int smem2 = (128 * 68 + 4 * 64 * 72 + 256) * 4;
    cudaFuncSetAttribute((const void*)gemm_mma_kernel<128, 64, true, false>,
                         cudaFuncAttributeMaxDynamicSharedMemorySize, smem1);
    cudaFuncSetAttribute((const void*)gemm_mma_kernel<64, 128, false, true>,
                         cudaFuncAttributeMaxDynamicSharedMemorySize, smem2);

    // ---- CSR build; layer-1 GEMM placed 4th (no CSR dependency) ----
    zero_kernel<<<(NN + 255) / 256, 256>>>();
    hist_kernel<<<edge_blocks, 256>>>(ei, E);
    scan_kernel<<<1, 1024>>>();
    gemm_mma_kernel<128, 64, true, false><<<g1_blocks, 256, smem1>>>(x, conv1_W, conv1_as, conv1_ad,
                                                                     nullptr, nullptr);
    sortedge_kernel<<<edge_blocks, 256>>>(ei, E);
    edgew_kernel<<<edge_blocks, 256>>>(E);
    aggregate_kernel<false, false><<<agg_blocks, 256>>>(conv1_b, bn_g, bn_b, bn_m, bn_v);

    // ---- layers 2..5 (fused proj GEMM) ----
    for (int l = 0; l < 4; l++) {
        gemm_mma_kernel<64, 128, false, true><<<g2_blocks, 256, smem2>>>(nullptr, convW + l * 4096,
                                                                         conv_as + l * 64, conv_ad + l * 64,
                                                                         projW + l * 4096, projb + l * 64);
        edgew_kernel<<<edge_blocks, 256>>>(E);
        if (l == 3)
            aggregate_kernel<true, true><<<agg_blocks, 256>>>(conv_b + l * 64,
                bn_g + (l + 1) * 64, bn_b + (l + 1) * 64, bn_m + (l + 1) * 64, bn_v + (l + 1) * 64);
        else
            aggregate_kernel<true, false><<<agg_blocks, 256>>>(conv_b + l * 64,
                bn_g + (l + 1) * 64, bn_b + (l + 1) * 64, bn_m + (l + 1) * 64, bn_v + (l + 1) * 64);
    }

    // ---- head ----
    head_kernel<<<1, 64>>>(hW1, hb1, hbn_g, hbn_b, hbn_m, hbn_v, hW2, hb2, (float*)d_out);
}